// round 7
// baseline (speedup 1.0000x reference)
#include <cuda_runtime.h>

#define BATCH   8
#define NPTS    4096
#define THREADS 128
#define PTS     16                       // query points per thread (8 packed pairs)
#define NPAIR   (PTS / 2)
#define PTS_BLK (THREADS * PTS)          // 2048
#define XT      (NPTS / PTS_BLK)         // 2 query tiles
#define NC      32                       // reference chunks
#define CH      (NPTS / NC)              // 128 reference pts per chunk
#define RBLKS   256                      // reduce blocks (16 db x 16 slices)

// Scratch (allocation-free contract).
__device__ float g_pmin[2 * BATCH * NC * NPTS];        // 8.4 MB partial mins
__device__ float g_psum[RBLKS];                        // 256 partial sums
__device__ int   g_ctr = 0;                            // last-block counter

// ---- packed f32x2 helpers -------------------------------------------------
__device__ __forceinline__ unsigned long long fma2(unsigned long long a,
                                                   unsigned long long b,
                                                   unsigned long long c) {
    unsigned long long d;
    asm("fma.rn.f32x2 %0, %1, %2, %3;" : "=l"(d) : "l"(a), "l"(b), "l"(c));
    return d;
}
__device__ __forceinline__ unsigned long long pack2(float lo, float hi) {
    unsigned long long v;
    asm("mov.b64 %0, {%1, %2};" : "=l"(v) : "f"(lo), "f"(hi));
    return v;
}
__device__ __forceinline__ float2 unpack2(unsigned long long v) {
    float2 r;
    asm("mov.b64 {%0, %1}, %2;" : "=f"(r.x), "=f"(r.y) : "l"(v));
    return r;
}

// ---- main all-pairs kernel ------------------------------------------------
// For each (dir, b, query-tile, ref-chunk): per-query min over chunk of
// (qq - 2*p.q); the p.p term is hoisted and re-added in the reduction.
__global__ void __launch_bounds__(THREADS, 6)
chamfer_main(const float* __restrict__ X, const float* __restrict__ Y) {
    // Pre-duplicated reference layout, 32 B/point:
    //   float4 #0 = (q0,q0, q1,q1), float4 #1 = (q2,q2, qq,qq)
    __shared__ float4 sq[CH * 2];

    int bid = blockIdx.x;
    int c   = bid & (NC - 1);   bid >>= 5;
    int xt  = bid & (XT - 1);   bid >>= 1;
    int b   = bid & (BATCH-1);  bid >>= 3;
    int dir = bid;                        // 0: x->y, 1: y->x

    const float* P  = dir ? Y : X;        // query set
    const float* Q  = dir ? X : Y;        // reference set
    const float* Qb = Q + b * 3 * NPTS;
    const float* Pb = P + b * 3 * NPTS;

    int tid = threadIdx.x;

    // Stage reference chunk (duplicated lanes for f32x2 broadcast). CH==THREADS.
    {
        int gm   = c * CH + tid;
        float q0 = Qb[gm];
        float q1 = Qb[gm + NPTS];
        float q2 = Qb[gm + 2 * NPTS];
        float qq = q0*q0 + q1*q1 + q2*q2;
        sq[tid * 2 + 0] = make_float4(q0, q0, q1, q1);
        sq[tid * 2 + 1] = make_float4(q2, q2, qq, qq);
    }
    __syncthreads();

    // 8 packed query pairs per thread, coefficients pre-scaled by -2.
    unsigned long long pa0[NPAIR], pa1[NPAIR], pa2[NPAIR];
    float mn[PTS];
    #pragma unroll
    for (int p = 0; p < NPAIR; p++) {
        int n0 = xt * PTS_BLK + (2*p)   * THREADS + tid;
        int n1 = xt * PTS_BLK + (2*p+1) * THREADS + tid;
        pa0[p] = pack2(-2.0f * Pb[n0],            -2.0f * Pb[n1]);
        pa1[p] = pack2(-2.0f * Pb[n0 + NPTS],     -2.0f * Pb[n1 + NPTS]);
        pa2[p] = pack2(-2.0f * Pb[n0 + 2*NPTS],   -2.0f * Pb[n1 + 2*NPTS]);
        mn[2*p] = 3.0e38f; mn[2*p+1] = 3.0e38f;
    }

    // Inner loop: 2 broadcast LDS.128 + 24 FFMA2 + 16 FMNMX per 16 pairs/thread.
    const ulonglong2* s2 = reinterpret_cast<const ulonglong2*>(sq);
    #pragma unroll 4
    for (int j = 0; j < CH; j++) {
        ulonglong2 A = s2[2*j];       // A.x={q0,q0}  A.y={q1,q1}
        ulonglong2 B = s2[2*j + 1];   // B.x={q2,q2}  B.y={qq,qq}
        #pragma unroll
        for (int p = 0; p < NPAIR; p++) {
            unsigned long long t =
                fma2(pa0[p], A.x, fma2(pa1[p], A.y, fma2(pa2[p], B.x, B.y)));
            float2 tf = unpack2(t);
            mn[2*p]   = fminf(mn[2*p],   tf.x);
            mn[2*p+1] = fminf(mn[2*p+1], tf.y);
        }
    }

    float* out = g_pmin + ((dir * BATCH + b) * NC + c) * NPTS;
    #pragma unroll
    for (int k = 0; k < PTS; k++)
        out[xt * PTS_BLK + k * THREADS + tid] = mn[k];
}

// ---- fused reduction + finalize -------------------------------------------
// 256 blocks x 256 threads = exactly one query point per thread: each thread
// mins its point over NC chunk-partials (32-deep MLP), adds back |p|^2,
// block-sums; the last block sums the 256 partials into the scalar mean.
__global__ void __launch_bounds__(256)
chamfer_reduce(const float* __restrict__ X, const float* __restrict__ Y,
               float* __restrict__ out) {
    int db  = blockIdx.x >> 4;            // 0..15  (dir*8 + b)
    int s   = blockIdx.x & 15;            // slice 0..15
    int dir = db >> 3;
    int b   = db & 7;
    const float* P  = dir ? Y : X;
    const float* Pb = P + b * 3 * NPTS;
    const float* pm = g_pmin + db * NC * NPTS;

    int n = s * 256 + threadIdx.x;        // one point per thread
    float v = pm[n];
    #pragma unroll
    for (int c = 1; c < NC; c++) v = fminf(v, pm[c * NPTS + n]);
    float p0 = Pb[n], p1 = Pb[n + NPTS], p2 = Pb[n + 2 * NPTS];
    float acc = v + p0*p0 + p1*p1 + p2*p2;

    __shared__ float red[256];
    __shared__ bool  is_last;
    red[threadIdx.x] = acc;
    __syncthreads();
    for (int st = 128; st > 0; st >>= 1) {
        if (threadIdx.x < st) red[threadIdx.x] += red[threadIdx.x + st];
        __syncthreads();
    }
    if (threadIdx.x == 0) {
        g_psum[blockIdx.x] = red[0];
        __threadfence();
        int prev = atomicAdd(&g_ctr, 1);
        is_last = (prev == RBLKS - 1);
    }
    __syncthreads();

    if (is_last) {
        // Deterministic finalize: one block sums the fixed 256-entry array.
        red[threadIdx.x] = *((volatile float*)&g_psum[threadIdx.x]);
        __syncthreads();
        for (int st = 128; st > 0; st >>= 1) {
            if (threadIdx.x < st) red[threadIdx.x] += red[threadIdx.x + st];
            __syncthreads();
        }
        if (threadIdx.x == 0) {
            out[0] = red[0] / (float)(NPTS * BATCH);
            g_ctr = 0;                    // reset for next graph replay
        }
    }
}

extern "C" void kernel_launch(void* const* d_in, const int* in_sizes, int n_in,
                              void* d_out, int out_size) {
    const float* x = (const float*)d_in[0];
    const float* y = (const float*)d_in[1];
    float* out = (float*)d_out;

    chamfer_main<<<2 * BATCH * XT * NC, THREADS>>>(x, y);
    chamfer_reduce<<<RBLKS, 256>>>(x, y, out);
}

// round 8
// speedup vs baseline: 1.2433x; 1.2433x over previous
#include <cuda_runtime.h>

#define BATCH   8
#define NPTS    4096
#define THREADS 128
#define PTS     8                        // query points per thread (4 packed pairs)
#define NPAIR   (PTS / 2)
#define PTS_BLK (THREADS * PTS)          // 1024
#define XT      (NPTS / PTS_BLK)         // 4 query tiles
#define NC      64                       // reference chunks
#define CH      (NPTS / NC)              // 64 reference pts per chunk
#define RBLKS   256                      // reduce blocks

// Scratch (allocation-free contract). g_key zero-init == "empty" under the
// inverted monotone encoding below; reduce resets it to 0 each replay.
__device__ unsigned g_key[2 * BATCH * NPTS];   // 512 KB encoded per-point mins
__device__ float    g_psum[RBLKS];
__device__ int      g_ctr = 0;

// ---- packed f32x2 helpers -------------------------------------------------
__device__ __forceinline__ unsigned long long fma2(unsigned long long a,
                                                   unsigned long long b,
                                                   unsigned long long c) {
    unsigned long long d;
    asm("fma.rn.f32x2 %0, %1, %2, %3;" : "=l"(d) : "l"(a), "l"(b), "l"(c));
    return d;
}
__device__ __forceinline__ unsigned long long pack2(float lo, float hi) {
    unsigned long long v;
    asm("mov.b64 %0, {%1, %2};" : "=l"(v) : "f"(lo), "f"(hi));
    return v;
}
__device__ __forceinline__ float2 unpack2(unsigned long long v) {
    float2 r;
    asm("mov.b64 {%0, %1}, %2;" : "=f"(r.x), "=f"(r.y) : "l"(v));
    return r;
}

// Order-preserving float -> uint map, then inverted so that min(f) == max(key)
// and key 0 means "no value yet" (any real key > 0).
__device__ __forceinline__ unsigned min_key(float f) {
    unsigned u = __float_as_uint(f);
    u ^= (unsigned)(((int)u >> 31)) | 0x80000000u;   // monotone: f order -> uint order
    return ~u;
}
__device__ __forceinline__ float key_to_float(unsigned key) {
    unsigned mono = ~key;
    unsigned bits = (mono & 0x80000000u) ? (mono ^ 0x80000000u) : ~mono;
    return __uint_as_float(bits);
}

// ---- main all-pairs kernel ------------------------------------------------
// For each (dir, b, query-tile, ref-chunk): per-query min over the chunk of
// (qq - 2*p.q)  [the p.p term is common to all chunks -> order-preserving,
// re-added in the reduction], folded globally via atomicMax on encoded keys.
__global__ void __launch_bounds__(THREADS)
chamfer_main(const float* __restrict__ X, const float* __restrict__ Y) {
    // Pre-duplicated reference layout, 32 B/point (+1 pad point for prefetch):
    //   float4 #0 = (q0,q0, q1,q1), float4 #1 = (q2,q2, qq,qq)
    __shared__ float4 sq[CH * 2 + 2];

    int bid = blockIdx.x;
    int c   = bid & (NC - 1);   bid >>= 6;
    int xt  = bid & (XT - 1);   bid >>= 2;
    int b   = bid & (BATCH-1);  bid >>= 3;
    int dir = bid;                        // 0: x->y, 1: y->x

    const float* P  = dir ? Y : X;        // query set
    const float* Q  = dir ? X : Y;        // reference set
    const float* Qb = Q + b * 3 * NPTS;
    const float* Pb = P + b * 3 * NPTS;

    int tid = threadIdx.x;

    // Stage reference chunk (duplicated lanes for f32x2 broadcast).
    if (tid < CH) {
        int gm   = c * CH + tid;
        float q0 = Qb[gm];
        float q1 = Qb[gm + NPTS];
        float q2 = Qb[gm + 2 * NPTS];
        float qq = q0*q0 + q1*q1 + q2*q2;
        sq[tid * 2 + 0] = make_float4(q0, q0, q1, q1);
        sq[tid * 2 + 1] = make_float4(q2, q2, qq, qq);
    }
    __syncthreads();

    // 4 packed query pairs per thread, coefficients pre-scaled by -2.
    unsigned long long pa0[NPAIR], pa1[NPAIR], pa2[NPAIR];
    float mn[PTS];
    #pragma unroll
    for (int p = 0; p < NPAIR; p++) {
        int n0 = xt * PTS_BLK + (2*p)   * THREADS + tid;
        int n1 = xt * PTS_BLK + (2*p+1) * THREADS + tid;
        pa0[p] = pack2(-2.0f * Pb[n0],            -2.0f * Pb[n1]);
        pa1[p] = pack2(-2.0f * Pb[n0 + NPTS],     -2.0f * Pb[n1 + NPTS]);
        pa2[p] = pack2(-2.0f * Pb[n0 + 2*NPTS],   -2.0f * Pb[n1 + 2*NPTS]);
        mn[2*p] = 3.0e38f; mn[2*p+1] = 3.0e38f;
    }

    // Inner loop with one-iteration register prefetch to hide LDS latency.
    const ulonglong2* s2 = reinterpret_cast<const ulonglong2*>(sq);
    ulonglong2 A = s2[0];                 // A.x={q0,q0}  A.y={q1,q1}
    ulonglong2 B = s2[1];                 // B.x={q2,q2}  B.y={qq,qq}
    #pragma unroll 2
    for (int j = 0; j < CH; j++) {
        ulonglong2 An = s2[2*j + 2];
        ulonglong2 Bn = s2[2*j + 3];
        #pragma unroll
        for (int p = 0; p < NPAIR; p++) {
            unsigned long long t =
                fma2(pa0[p], A.x, fma2(pa1[p], A.y, fma2(pa2[p], B.x, B.y)));
            float2 tf = unpack2(t);
            mn[2*p]   = fminf(mn[2*p],   tf.x);
            mn[2*p+1] = fminf(mn[2*p+1], tf.y);
        }
        A = An; B = Bn;
    }

    // Fold chunk mins into the global per-point min (fire-and-forget REDG.MAX).
    unsigned* gk = g_key + (dir * BATCH + b) * NPTS + xt * PTS_BLK;
    #pragma unroll
    for (int k = 0; k < PTS; k++)
        atomicMax(&gk[k * THREADS + tid], min_key(mn[k]));
}

// ---- fused reduction + finalize -------------------------------------------
// One thread per (db, point): decode the folded min, add back |p|^2, reset the
// key for the next graph replay, block-sum; last block writes the scalar mean.
__global__ void __launch_bounds__(256)
chamfer_reduce(const float* __restrict__ X, const float* __restrict__ Y,
               float* __restrict__ out) {
    int gid = blockIdx.x * 256 + threadIdx.x;   // 0..65535
    int db  = gid >> 12;                        // dir*8 + b
    int n   = gid & (NPTS - 1);
    int dir = db >> 3;
    int b   = db & 7;
    const float* P  = dir ? Y : X;
    const float* Pb = P + b * 3 * NPTS;

    unsigned key = g_key[gid];
    g_key[gid] = 0u;                            // reset for next replay
    float v  = key_to_float(key);
    float p0 = Pb[n], p1 = Pb[n + NPTS], p2 = Pb[n + 2 * NPTS];
    float acc = v + p0*p0 + p1*p1 + p2*p2;

    __shared__ float red[256];
    __shared__ bool  is_last;
    red[threadIdx.x] = acc;
    __syncthreads();
    for (int st = 128; st > 0; st >>= 1) {
        if (threadIdx.x < st) red[threadIdx.x] += red[threadIdx.x + st];
        __syncthreads();
    }
    if (threadIdx.x == 0) {
        g_psum[blockIdx.x] = red[0];
        __threadfence();
        int prev = atomicAdd(&g_ctr, 1);
        is_last = (prev == RBLKS - 1);
    }
    __syncthreads();

    if (is_last) {
        red[threadIdx.x] = *((volatile float*)&g_psum[threadIdx.x]);
        __syncthreads();
        for (int st = 128; st > 0; st >>= 1) {
            if (threadIdx.x < st) red[threadIdx.x] += red[threadIdx.x + st];
            __syncthreads();
        }
        if (threadIdx.x == 0) {
            out[0] = red[0] / (float)(NPTS * BATCH);
            g_ctr = 0;                          // reset for next replay
        }
    }
}

extern "C" void kernel_launch(void* const* d_in, const int* in_sizes, int n_in,
                              void* d_out, int out_size) {
    const float* x = (const float*)d_in[0];
    const float* y = (const float*)d_in[1];
    float* out = (float*)d_out;

    chamfer_main<<<2 * BATCH * XT * NC, THREADS>>>(x, y);
    chamfer_reduce<<<RBLKS, 256>>>(x, y, out);
}